// round 7
// baseline (speedup 1.0000x reference)
#include <cuda_runtime.h>
#include <cstdint>

#define NN 100000
#define EE 1600000
#define DD 128
#define LL 5
#define GG 128
#define TT 10
#define NBOND 4
#define BN_EPS 1e-5f
#define NB_AGG 592
#define NCHUNK 98
#define MTILES 782          // ceil(NN/128)
#define SPAD 136            // padded smem row stride (floats)

// ---------------- scratch (device globals) -----------------------------------
__device__ float g_hx [NN * DD];
__device__ float g_h2 [NN * DD];
__device__ float g_deg [NN];
__device__ float g_dinv[NN];
__device__ int   g_indeg[NN];
__device__ int   g_cur  [NN];
__device__ int   g_rowptr[NN + 1];
__device__ int   g_blocksum[NCHUNK];
__device__ int   g_blockoff[NCHUNK];
__device__ int   g_epack[EE];
__device__ float g_enorm[EE];
__device__ float g_partS [NB_AGG * DD];
__device__ float g_partSS[NB_AGG * DD];
__device__ float g_bnp[2 * DD];
__device__ float g_pool[GG * DD];
__device__ float g_cnt [GG];

// ---------------- tf32 helpers ------------------------------------------------
__device__ __forceinline__ uint32_t f2tf(float v) {
    uint32_t r;
    asm("cvt.rna.tf32.f32 %0, %1;" : "=r"(r) : "f"(v));
    return r;
}
__device__ __forceinline__ void split_tf32(float v, uint32_t& hi, uint32_t& lo) {
    hi = f2tf(v);
    float rem = v - __uint_as_float(hi);
    lo = f2tf(rem);
}
__device__ __forceinline__ void mma_tf32(float c[4], const uint32_t a[4],
                                         uint32_t b0, uint32_t b1) {
    asm("mma.sync.aligned.m16n8k8.row.col.f32.tf32.tf32.f32 "
        "{%0,%1,%2,%3}, {%4,%5,%6,%7}, {%8,%9}, {%0,%1,%2,%3};"
        : "+f"(c[0]), "+f"(c[1]), "+f"(c[2]), "+f"(c[3])
        : "r"(a[0]), "r"(a[1]), "r"(a[2]), "r"(a[3]), "r"(b0), "r"(b1));
}

// ---------------- prolog ------------------------------------------------------
__global__ void k_init() {
    int i = blockIdx.x * blockDim.x + threadIdx.x;
    if (i < NN) { g_deg[i] = 1.0f; g_indeg[i] = 0; g_cur[i] = 0; }
    if (i < GG * DD) g_pool[i] = 0.f;
    if (i < GG) g_cnt[i] = 0.f;
}
__global__ void k_count(const int* __restrict__ row, const int* __restrict__ col) {
    int e = blockIdx.x * blockDim.x + threadIdx.x;
    if (e < EE) {
        atomicAdd(&g_deg[row[e]], 1.0f);
        atomicAdd(&g_indeg[col[e]], 1);
    }
}
__global__ void k_dinv() {
    int i = blockIdx.x * blockDim.x + threadIdx.x;
    if (i < NN) g_dinv[i] = rsqrtf(g_deg[i]);
}
__global__ void k_scan1() {
    __shared__ int sm[1024];
    int tid = threadIdx.x;
    int i = blockIdx.x * 1024 + tid;
    int v = (i < NN) ? g_indeg[i] : 0;
    sm[tid] = v;
    __syncthreads();
    for (int off = 1; off < 1024; off <<= 1) {
        int t = (tid >= off) ? sm[tid - off] : 0;
        __syncthreads();
        sm[tid] += t;
        __syncthreads();
    }
    if (i < NN) g_rowptr[i] = sm[tid] - v;
    if (tid == 1023) g_blocksum[blockIdx.x] = sm[1023];
}
__global__ void k_scan2() {
    if (threadIdx.x == 0) {
        int run = 0;
        for (int bk = 0; bk < NCHUNK; bk++) { g_blockoff[bk] = run; run += g_blocksum[bk]; }
    }
}
__global__ void k_scan3() {
    int i = blockIdx.x * blockDim.x + threadIdx.x;
    if (i < NN) g_rowptr[i] += g_blockoff[i >> 10];
    if (i == 0) g_rowptr[NN] = EE;
}
__global__ void k_scatter(const int* __restrict__ row, const int* __restrict__ col,
                          const int* __restrict__ ea) {
    int e = blockIdx.x * blockDim.x + threadIdx.x;
    if (e >= EE) return;
    int r = row[e], c = col[e], a = ea[e];
    float nv = g_dinv[r] * g_dinv[c];
    int pos = g_rowptr[c] + atomicAdd(&g_cur[c], 1);
    g_epack[pos] = r | (a << 17);
    g_enorm[pos] = nv;
}

// ---------------- tensor-core linear: hx = act(h) @ W + b --------------------
// 3xTF32 via mma.sync m16n8k8. Block: 128 rows, 256 threads (8 warps x 16 rows).
__global__ void __launch_bounds__(256, 1) k_linear_tc(
        const float* __restrict__ h, const float* __restrict__ W,
        const float* __restrict__ b, int use_bn) {
    extern __shared__ float smem[];
    float* sWhi = smem;                    // [128][SPAD]
    float* sWlo = smem + 128 * SPAD;
    float* sA   = smem + 2 * 128 * SPAD;
    int tid = threadIdx.x;
    int m0 = blockIdx.x * 128;
    const float4* h4 = use_bn ? (const float4*)g_h2 : (const float4*)h;

    // stage W, pre-split hi/lo
    for (int i = tid; i < 128 * 32; i += 256) {
        int r = i >> 5, c4 = i & 31;
        float4 w = ((const float4*)W)[r * 32 + c4];
        uint32_t hx_, lx_;
        float4 whi, wlo;
        split_tf32(w.x, hx_, lx_); whi.x = __uint_as_float(hx_); wlo.x = __uint_as_float(lx_);
        split_tf32(w.y, hx_, lx_); whi.y = __uint_as_float(hx_); wlo.y = __uint_as_float(lx_);
        split_tf32(w.z, hx_, lx_); whi.z = __uint_as_float(hx_); wlo.z = __uint_as_float(lx_);
        split_tf32(w.w, hx_, lx_); whi.w = __uint_as_float(hx_); wlo.w = __uint_as_float(lx_);
        *(float4*)(sWhi + r * SPAD + c4 * 4) = whi;
        *(float4*)(sWlo + r * SPAD + c4 * 4) = wlo;
    }
    // stage A tile with fused BN+relu
    float4 z4 = {0, 0, 0, 0};
    for (int i = tid; i < 128 * 32; i += 256) {
        int r = i >> 5, c4 = i & 31;
        int gr = m0 + r;
        float4 t = (gr < NN) ? h4[(size_t)gr * 32 + c4] : z4;
        if (use_bn && gr < NN) {
            float4 sc = ((const float4*)g_bnp)[c4];
            float4 sh = ((const float4*)g_bnp)[32 + c4];
            t.x = fmaxf(t.x * sc.x + sh.x, 0.f);
            t.y = fmaxf(t.y * sc.y + sh.y, 0.f);
            t.z = fmaxf(t.z * sc.z + sh.z, 0.f);
            t.w = fmaxf(t.w * sc.w + sh.w, 0.f);
        }
        *(float4*)(sA + r * SPAD + c4 * 4) = t;
    }
    __syncthreads();

    int w = tid >> 5;
    int lane = tid & 31;
    int gid = lane >> 2;          // 0..7
    int tig = lane & 3;           // 0..3
    int mw = w * 16;              // warp row base within tile

    float acc[16][4];
#pragma unroll
    for (int nb = 0; nb < 16; nb++) {
        acc[nb][0] = 0.f; acc[nb][1] = 0.f; acc[nb][2] = 0.f; acc[nb][3] = 0.f;
    }

    for (int ks = 0; ks < 16; ks++) {
        uint32_t ah[4], al[4];
        // A fragment: rows mw+gid, mw+gid+8; cols ks*8+tig, +4
        split_tf32(sA[(mw + gid)     * SPAD + ks * 8 + tig],     ah[0], al[0]);
        split_tf32(sA[(mw + gid + 8) * SPAD + ks * 8 + tig],     ah[1], al[1]);
        split_tf32(sA[(mw + gid)     * SPAD + ks * 8 + tig + 4], ah[2], al[2]);
        split_tf32(sA[(mw + gid + 8) * SPAD + ks * 8 + tig + 4], ah[3], al[3]);
#pragma unroll
        for (int nb = 0; nb < 16; nb++) {
            int k0 = ks * 8 + tig;
            int cn = nb * 8 + gid;
            uint32_t b0h = __float_as_uint(sWhi[k0 * SPAD + cn]);
            uint32_t b1h = __float_as_uint(sWhi[(k0 + 4) * SPAD + cn]);
            uint32_t b0l = __float_as_uint(sWlo[k0 * SPAD + cn]);
            uint32_t b1l = __float_as_uint(sWlo[(k0 + 4) * SPAD + cn]);
            mma_tf32(acc[nb], ah, b0h, b1h);
            mma_tf32(acc[nb], ah, b0l, b1l);
            mma_tf32(acc[nb], al, b0h, b1h);
        }
    }

    // epilogue: add bias, store
    int r0 = m0 + mw + gid;
    int r1 = r0 + 8;
#pragma unroll
    for (int nb = 0; nb < 16; nb++) {
        int cc = nb * 8 + 2 * tig;
        float2 bv = *(const float2*)(b + cc);
        if (r0 < NN) {
            float2 o = {acc[nb][0] + bv.x, acc[nb][1] + bv.y};
            *(float2*)(g_hx + (size_t)r0 * 128 + cc) = o;
        }
        if (r1 < NN) {
            float2 o = {acc[nb][2] + bv.x, acc[nb][3] + bv.y};
            *(float2*)(g_hx + (size_t)r1 * 128 + cc) = o;
        }
    }
}

// ---------------- fused aggregation: messages + self + BN partial stats -------
__global__ void __launch_bounds__(256) k_agg(const float* __restrict__ bond,
                                             const float* __restrict__ root) {
    __shared__ float sS [8][DD];
    __shared__ float sSS[8][DD];
    int lane = threadIdx.x & 31;
    int wid  = threadIdx.x >> 5;
    const float4* hx4 = (const float4*)g_hx;
    const float4* bd4 = (const float4*)bond;
    float4 rt = ((const float4*)root)[lane];
    float4 s4  = {0, 0, 0, 0};
    float4 ss4 = {0, 0, 0, 0};

    for (int c = blockIdx.x * 8 + wid; c < NN; c += NB_AGG * 8) {
        float4 acc = {0, 0, 0, 0};
        int e0 = g_rowptr[c], e1 = g_rowptr[c + 1];
        for (int e = e0; e < e1; e++) {
            int p = g_epack[e];
            float nv = g_enorm[e];
            int r = p & 0x1FFFF;
            int a = p >> 17;
            float4 hv = hx4[(size_t)r * 32 + lane];
            float4 bd = bd4[a * 32 + lane];
            acc.x += nv * fmaxf(hv.x + bd.x, 0.f);
            acc.y += nv * fmaxf(hv.y + bd.y, 0.f);
            acc.z += nv * fmaxf(hv.z + bd.z, 0.f);
            acc.w += nv * fmaxf(hv.w + bd.w, 0.f);
        }
        float4 hv = hx4[(size_t)c * 32 + lane];
        float inv = 1.0f / g_deg[c];
        acc.x += fmaxf(hv.x + rt.x, 0.f) * inv;
        acc.y += fmaxf(hv.y + rt.y, 0.f) * inv;
        acc.z += fmaxf(hv.z + rt.z, 0.f) * inv;
        acc.w += fmaxf(hv.w + rt.w, 0.f) * inv;
        ((float4*)g_h2)[(size_t)c * 32 + lane] = acc;
        s4.x += acc.x; s4.y += acc.y; s4.z += acc.z; s4.w += acc.w;
        ss4.x += acc.x * acc.x; ss4.y += acc.y * acc.y;
        ss4.z += acc.z * acc.z; ss4.w += acc.w * acc.w;
    }
    sS [wid][lane * 4 + 0] = s4.x;  sS [wid][lane * 4 + 1] = s4.y;
    sS [wid][lane * 4 + 2] = s4.z;  sS [wid][lane * 4 + 3] = s4.w;
    sSS[wid][lane * 4 + 0] = ss4.x; sSS[wid][lane * 4 + 1] = ss4.y;
    sSS[wid][lane * 4 + 2] = ss4.z; sSS[wid][lane * 4 + 3] = ss4.w;
    __syncthreads();
    if (threadIdx.x < DD) {
        float s = 0.f, ss = 0.f;
#pragma unroll
        for (int ww = 0; ww < 8; ww++) { s += sS[ww][threadIdx.x]; ss += sSS[ww][threadIdx.x]; }
        g_partS [blockIdx.x * DD + threadIdx.x] = s;
        g_partSS[blockIdx.x * DD + threadIdx.x] = ss;
    }
}

__global__ void k_bn_finalize(const float* __restrict__ gamma, const float* __restrict__ beta) {
    __shared__ float rS[4][DD], rSS[4][DD];
    int j = threadIdx.x & 127;
    int part = threadIdx.x >> 7;
    float s = 0.f, ss = 0.f;
    for (int bidx = part; bidx < NB_AGG; bidx += 4) {
        s  += g_partS [bidx * DD + j];
        ss += g_partSS[bidx * DD + j];
    }
    rS[part][j] = s; rSS[part][j] = ss;
    __syncthreads();
    if (part == 0) {
        s  = rS[0][j]  + rS[1][j]  + rS[2][j]  + rS[3][j];
        ss = rSS[0][j] + rSS[1][j] + rSS[2][j] + rSS[3][j];
        float mu  = s * (1.0f / NN);
        float var = ss * (1.0f / NN) - mu * mu;
        float scv = gamma[j] * rsqrtf(var + BN_EPS);
        g_bnp[j]      = scv;
        g_bnp[DD + j] = beta[j] - mu * scv;
    }
}

// ---------------- pooling (BN apply fused) + output ---------------------------
__global__ void k_pool(const int* __restrict__ batch) {
    int lane = threadIdx.x & 31;
    int node = (blockIdx.x * blockDim.x + threadIdx.x) >> 5;
    if (node >= NN) return;
    int g = batch[node];
    float4 v  = ((const float4*)g_h2)[(size_t)node * 32 + lane];
    float4 sc = ((const float4*)g_bnp)[lane];
    float4 sh = ((const float4*)g_bnp)[32 + lane];
    float hx = fmaxf(v.x * sc.x + sh.x, 0.f);
    float hy = fmaxf(v.y * sc.y + sh.y, 0.f);
    float hz = fmaxf(v.z * sc.z + sh.z, 0.f);
    float hw = fmaxf(v.w * sc.w + sh.w, 0.f);
    float* dst = g_pool + (size_t)g * 128 + lane * 4;
    asm volatile("red.global.add.v4.f32 [%0], {%1,%2,%3,%4};"
                 :: "l"(dst), "f"(hx), "f"(hy), "f"(hz), "f"(hw) : "memory");
    if (lane == 0) atomicAdd(&g_cnt[g], 1.0f);
}
__global__ void k_out(const float* __restrict__ Wout, const float* __restrict__ bout,
                      float* __restrict__ out) {
    int g = blockIdx.x, j = threadIdx.x;
    __shared__ float red[DD];
    float c  = fmaxf(g_cnt[g], 1.0f);
    float hg = g_pool[(size_t)g * 128 + j] / c;
#pragma unroll
    for (int t = 0; t < TT; t++) {
        red[j] = hg * Wout[j * TT + t];
        __syncthreads();
        for (int s = 64; s > 0; s >>= 1) {
            if (j < s) red[j] += red[j + s];
            __syncthreads();
        }
        if (j == 0) out[g * TT + t] = red[0] + bout[t];
        __syncthreads();
    }
}

// ---------------- host --------------------------------------------------------
extern "C" void kernel_launch(void* const* d_in, const int* in_sizes, int n_in,
                              void* d_out, int out_size) {
    const float* x     = (const float*)d_in[0];
    const int*   ei    = (const int*)  d_in[1];
    const int*   ea    = (const int*)  d_in[2];
    const int*   batch = (const int*)  d_in[3];
    const float* W     = (const float*)d_in[4];
    const float* b     = (const float*)d_in[5];
    const float* root  = (const float*)d_in[6];
    const float* bond  = (const float*)d_in[7];
    const float* gamma = (const float*)d_in[8];
    const float* beta  = (const float*)d_in[9];
    const float* Wout  = (const float*)d_in[10];
    const float* bout  = (const float*)d_in[11];
    float* out = (float*)d_out;

    const int* row = ei;
    const int* col = ei + EE;

    const int smem_lin = 3 * 128 * SPAD * (int)sizeof(float);   // 208896 B
    cudaFuncSetAttribute(k_linear_tc, cudaFuncAttributeMaxDynamicSharedMemorySize, smem_lin);

    k_init<<<(NN + 255) / 256, 256>>>();
    k_count<<<(EE + 255) / 256, 256>>>(row, col);
    k_dinv<<<(NN + 255) / 256, 256>>>();
    k_scan1<<<NCHUNK, 1024>>>();
    k_scan2<<<1, 32>>>();
    k_scan3<<<(NN + 255) / 256, 256>>>();
    k_scatter<<<(EE + 255) / 256, 256>>>(row, col, ea);

    for (int l = 0; l < LL; l++) {
        const float* Wl = W     + (size_t)l * DD * DD;
        const float* bl = b     + (size_t)l * DD;
        const float* rl = root  + (size_t)l * DD;
        const float* el = bond  + (size_t)l * NBOND * DD;
        const float* gl = gamma + (size_t)l * DD;
        const float* tl = beta  + (size_t)l * DD;

        k_linear_tc<<<MTILES, 256, smem_lin>>>(x, Wl, bl, l == 0 ? 0 : 1);
        k_agg<<<NB_AGG, 256>>>(el, rl);
        k_bn_finalize<<<1, 512>>>(gl, tl);
    }

    k_pool<<<(NN + 7) / 8, 256>>>(batch);
    k_out<<<GG, DD>>>(Wout, bout, out);
}